// round 7
// baseline (speedup 1.0000x reference)
#include <cuda_runtime.h>
#include <cuda_bf16.h>

#define NCTA 256
#define NT 320
#define TT 1024
#define BB 128
#define HH 256
#define GSZ 64          // CTAs per row-group

__device__ float g_h[BB * HH];
__device__ float g_u[BB * HH];
__device__ unsigned g_flags[4][GSZ][8];

__device__ __forceinline__ float4 ldcg4(const float4* p) {
    float4 v;
    asm volatile("ld.global.cg.v4.f32 {%0,%1,%2,%3}, [%4];"
                 : "=f"(v.x), "=f"(v.y), "=f"(v.z), "=f"(v.w) : "l"(p));
    return v;
}
__device__ __forceinline__ float ldcg1(const float* p) {
    float v;
    asm volatile("ld.global.cg.f32 %0, [%1];" : "=f"(v) : "l"(p));
    return v;
}
__device__ __forceinline__ float fast_tanh(float x) {
    float ax = fabsf(x);
    float e = __expf(2.0f * ax);
    float r = 1.0f - 2.0f / (e + 1.0f);
    return copysignf(r, x);
}
__device__ __forceinline__ float fast_sigmoid(float x) {
    return 1.0f / (1.0f + __expf(-x));
}

// Row-group barrier: 64 CTAs (same mi). Each CTA stores its own epoch flag;
// warp 0 polls all 64 flags (2 per lane).
__device__ __forceinline__ void group_bar(unsigned* fl, int nj, unsigned base, unsigned ep) {
    __syncthreads();
    if (threadIdx.x < 32) {
        if (threadIdx.x == 0) {
            asm volatile("fence.acq_rel.gpu;" ::: "memory");
            asm volatile("st.relaxed.gpu.global.u32 [%0], %1;"
                         :: "l"(fl + nj * 8), "r"(base + ep) : "memory");
        }
        unsigned v1, v2;
        unsigned* p1 = fl + threadIdx.x * 8;
        unsigned* p2 = fl + (threadIdx.x + 32) * 8;
        do {
            asm volatile("ld.relaxed.gpu.global.u32 %0, [%1];"
                         : "=r"(v1) : "l"(p1) : "memory");
            asm volatile("ld.relaxed.gpu.global.u32 %0, [%1];"
                         : "=r"(v2) : "l"(p2) : "memory");
        } while (__any_sync(0xffffffffu, ((v1 - base) < ep) || ((v2 - base) < ep)));
        asm volatile("fence.acq_rel.gpu;" ::: "memory");
    }
    __syncthreads();
}

// SMEM layout (floats)
#define OFF_W1S 0                         // [256][20]
#define OFF_W2S (OFF_W1S + 256 * 20)      // [256][8]
#define OFF_H4S (OFF_W2S + 256 * 8)       // [64][32][4]
#define OFF_U4S (OFF_H4S + 8192)          // [64][32][4]
#define OFF_S1  (OFF_U4S + 8192)          // [2][20][33]  k-half partials
#define OFF_S2  (OFF_S1 + 2 * 20 * 33)    // [4][8][33]   k-quarter partials
#define OFF_AMP (OFF_S2 + 4 * 8 * 33)     // [32]
#define OFF_COS (OFF_AMP + 32)
#define OFF_SIN (OFF_COS + 32)
#define OFF_W0  (OFF_SIN + 32)            // [3][4]
#define OFF_B1  (OFF_W0 + 12)             // [3][4]
#define OFF_BZ  (OFF_B1 + 12)             // [4]
#define OFF_BH  (OFF_BZ + 4)              // [4]
#define OFF_WOF (OFF_BH + 4)              // [256][2]
#define OFF_BO  (OFF_WOF + 512)           // [2]
#define SMEM_FLOATS (OFF_BO + 2)
#define SMEM_BYTES (SMEM_FLOATS * 4)

__global__ void __launch_bounds__(NT, 2) pgjanet_kernel(
    const float* __restrict__ x,   const float* __restrict__ h0,
    const float* __restrict__ Wa,  const float* __restrict__ ba,
    const float* __restrict__ Wp1, const float* __restrict__ bp1,
    const float* __restrict__ Wp2, const float* __restrict__ bp2,
    const float* __restrict__ Wz,  const float* __restrict__ bz,
    const float* __restrict__ Wh,  const float* __restrict__ bh,
    const float* __restrict__ Wo,  const float* __restrict__ bo,
    float* __restrict__ out)
{
    extern __shared__ float sm[];
    float* W1s = sm + OFF_W1S;
    float* W2s = sm + OFF_W2S;
    float* h4s = sm + OFF_H4S;
    float* u4s = sm + OFF_U4S;
    float* S1  = sm + OFF_S1;
    float* S2  = sm + OFF_S2;
    float* s_amp = sm + OFF_AMP;
    float* s_cos = sm + OFF_COS;
    float* s_sin = sm + OFF_SIN;
    float* s_w0  = sm + OFF_W0;
    float* s_b1  = sm + OFF_B1;
    float* s_bz  = sm + OFF_BZ;
    float* s_bh  = sm + OFF_BH;
    float* s_Wo  = sm + OFF_WOF;
    float* s_bo  = sm + OFF_BO;

    const int tid  = threadIdx.x;
    const int lane = tid & 31;
    const int wid  = tid >> 5;
    const int nj = blockIdx.x & (GSZ - 1);  // column slice (4 cols)
    const int mi = blockIdx.x / GSZ;        // row group (32 rows)
    const int j0 = nj * 4;
    const int r0 = mi * 32;

    unsigned* fl = &g_flags[mi][0][0];

    unsigned base = 0;
    if (tid < 32)
        asm volatile("ld.relaxed.gpu.global.u32 %0, [%1];"
                     : "=r"(base) : "l"(fl + nj * 8) : "memory");

    // ---- preload loop-invariant weights into SMEM ----
    for (int idx = tid; idx < 256 * 20; idx += NT) {
        int k = idx / 20, nn = idx % 20;
        int mat = nn >> 2, j = j0 + (nn & 3);
        float v;
        if      (mat == 0) v = Wa [(1 + k) * HH + j];
        else if (mat == 1) v = Wp1[(1 + k) * HH + j];
        else if (mat == 2) v = Wp2[(1 + k) * HH + j];
        else if (mat == 3) v = Wz [(HH + k) * HH + j];
        else               v = Wh [(HH + k) * HH + j];
        W1s[k * 20 + nn] = v;
    }
    for (int idx = tid; idx < 256 * 8; idx += NT) {
        int k = idx / 8, nn = idx % 8;
        int j = j0 + (nn & 3);
        W2s[k * 8 + nn] = (nn < 4) ? Wz[k * HH + j] : Wh[k * HH + j];
    }
    for (int idx = tid; idx < 512; idx += NT) s_Wo[idx] = Wo[idx];
    if (tid < 4) {
        int j = j0 + tid;
        s_w0[tid]      = Wa [j];  s_w0[4 + tid]  = Wp1[j];  s_w0[8 + tid] = Wp2[j];
        s_b1[tid]      = ba [j];  s_b1[4 + tid]  = bp1[j];  s_b1[8 + tid] = bp2[j];
        s_bz[tid] = bz[j];        s_bh[tid] = bh[j];
    }
    if (tid == 0) { s_bo[0] = bo[0]; s_bo[1] = bo[1]; }

    unsigned ep = 0;

    for (int t = 0; t < TT; ++t) {
        // ---- stage 1: load h tile into SMEM ([kc][row][4]) ----
        const float* hsrc = (t == 0) ? h0 : g_h;
        for (int idx = tid; idx < 32 * 64; idx += NT) {
            int r = idx >> 6, kc = idx & 63;
            float4 v = ldcg4((const float4*)(hsrc + (r0 + r) * HH) + kc);
            *(float4*)&h4s[(kc * 32 + r) * 4] = v;
        }
        if (tid < 32) {
            const float* xp = x + (((r0 + tid) * TT) + t) * 2;
            float amp = __ldg(xp), ph = __ldg(xp + 1);
            s_amp[tid] = amp;
            float sv, cv; sincosf(ph, &sv, &cv);
            s_sin[tid] = sv; s_cos[tid] = cv;
        }
        __syncthreads();

        // ---- GEMM1: 10 warps = 5 col-groups (4 cols) x 2 k-halves ----
        {
            int cg = wid % 5, kh = wid / 5;
            float a0 = 0.f, a1 = 0.f, a2 = 0.f, a3 = 0.f;
            const float* wp = W1s + cg * 4;
            #pragma unroll 4
            for (int kc = kh * 32; kc < kh * 32 + 32; ++kc) {
                float4 hv = *(const float4*)&h4s[(kc * 32 + lane) * 4];
                float4 w;
                w = *(const float4*)&wp[(kc * 4 + 0) * 20];
                a0 += hv.x * w.x; a1 += hv.x * w.y; a2 += hv.x * w.z; a3 += hv.x * w.w;
                w = *(const float4*)&wp[(kc * 4 + 1) * 20];
                a0 += hv.y * w.x; a1 += hv.y * w.y; a2 += hv.y * w.z; a3 += hv.y * w.w;
                w = *(const float4*)&wp[(kc * 4 + 2) * 20];
                a0 += hv.z * w.x; a1 += hv.z * w.y; a2 += hv.z * w.z; a3 += hv.z * w.w;
                w = *(const float4*)&wp[(kc * 4 + 3) * 20];
                a0 += hv.w * w.x; a1 += hv.w * w.y; a2 += hv.w * w.z; a3 += hv.w * w.w;
            }
            float* s = S1 + kh * 20 * 33;
            s[(cg * 4 + 0) * 33 + lane] = a0;
            s[(cg * 4 + 1) * 33 + lane] = a1;
            s[(cg * 4 + 2) * 33 + lane] = a2;
            s[(cg * 4 + 3) * 33 + lane] = a3;
        }
        __syncthreads();

        // ---- epilogue 1: a, p1, p2 -> u (128 threads) ----
        if (tid < 128) {
            int jj = tid & 3, r = tid >> 2;
            float a  = fast_tanh(S1[(0 + jj) * 33 + r] + S1[660 + (0 + jj) * 33 + r]
                                 + s_amp[r] * s_w0[jj]     + s_b1[jj]);
            float p1 = fast_tanh(S1[(4 + jj) * 33 + r] + S1[660 + (4 + jj) * 33 + r]
                                 + s_cos[r] * s_w0[4 + jj] + s_b1[4 + jj]);
            float p2 = fast_tanh(S1[(8 + jj) * 33 + r] + S1[660 + (8 + jj) * 33 + r]
                                 + s_sin[r] * s_w0[8 + jj] + s_b1[8 + jj]);
            g_u[(r0 + r) * HH + j0 + jj] =
                a * p1 * p2 * (1.f - a) * (1.f - p1) * (1.f - p2);
        }
        group_bar(fl, nj, base, ++ep);

        // ---- stage 2: load u tile ----
        for (int idx = tid; idx < 32 * 64; idx += NT) {
            int r = idx >> 6, kc = idx & 63;
            float4 v = ldcg4((const float4*)(g_u + (r0 + r) * HH) + kc);
            *(float4*)&u4s[(kc * 32 + r) * 4] = v;
        }
        __syncthreads();

        // ---- GEMM2: warps 0-7 = 2 col-groups (4 cols) x 4 k-quarters ----
        if (wid < 8) {
            int cg2 = wid & 1, kq = wid >> 1;
            float a0 = 0.f, a1 = 0.f, a2 = 0.f, a3 = 0.f;
            const float* wp = W2s + cg2 * 4;
            #pragma unroll 4
            for (int kc = kq * 16; kc < kq * 16 + 16; ++kc) {
                float4 uv = *(const float4*)&u4s[(kc * 32 + lane) * 4];
                float4 w;
                w = *(const float4*)&wp[(kc * 4 + 0) * 8];
                a0 += uv.x * w.x; a1 += uv.x * w.y; a2 += uv.x * w.z; a3 += uv.x * w.w;
                w = *(const float4*)&wp[(kc * 4 + 1) * 8];
                a0 += uv.y * w.x; a1 += uv.y * w.y; a2 += uv.y * w.z; a3 += uv.y * w.w;
                w = *(const float4*)&wp[(kc * 4 + 2) * 8];
                a0 += uv.z * w.x; a1 += uv.z * w.y; a2 += uv.z * w.z; a3 += uv.z * w.w;
                w = *(const float4*)&wp[(kc * 4 + 3) * 8];
                a0 += uv.w * w.x; a1 += uv.w * w.y; a2 += uv.w * w.z; a3 += uv.w * w.w;
            }
            float* s = S2 + kq * 8 * 33;
            s[(cg2 * 4 + 0) * 33 + lane] = a0;
            s[(cg2 * 4 + 1) * 33 + lane] = a1;
            s[(cg2 * 4 + 2) * 33 + lane] = a2;
            s[(cg2 * 4 + 3) * 33 + lane] = a3;
        } else if (nj == 0 && t >= 1) {
            // warps 8,9: output projection for step t-1 from h4s
            #pragma unroll
            for (int it = 0; it < 4; ++it) {
                int item = it * 64 + (wid - 8) * 32 + lane;
                int r = item >> 3, kk = item & 7;
                float o0 = 0.f, o1 = 0.f;
                for (int k = kk * 32; k < kk * 32 + 32; ++k) {
                    float v = h4s[(k >> 2) * 128 + r * 4 + (k & 3)];
                    o0 += v * s_Wo[k * 2];
                    o1 += v * s_Wo[k * 2 + 1];
                }
                o0 += __shfl_xor_sync(0xffffffffu, o0, 1);
                o0 += __shfl_xor_sync(0xffffffffu, o0, 2);
                o0 += __shfl_xor_sync(0xffffffffu, o0, 4);
                o1 += __shfl_xor_sync(0xffffffffu, o1, 1);
                o1 += __shfl_xor_sync(0xffffffffu, o1, 2);
                o1 += __shfl_xor_sync(0xffffffffu, o1, 4);
                if (kk == 0) {
                    float* op = out + (((r0 + r) * TT) + (t - 1)) * 2;
                    op[0] = o0 + s_bo[0];
                    op[1] = o1 + s_bo[1];
                }
            }
        }
        __syncthreads();

        // ---- epilogue 2: z, h_cand, h_new (128 threads) ----
        if (tid < 128) {
            int jj = tid & 3, r = tid >> 2;
            int j = j0 + jj;
            float zp = S2[0 * 264 + jj * 33 + r] + S2[1 * 264 + jj * 33 + r]
                     + S2[2 * 264 + jj * 33 + r] + S2[3 * 264 + jj * 33 + r]
                     + S1[(12 + jj) * 33 + r] + S1[660 + (12 + jj) * 33 + r]
                     + s_bz[jj];
            float hp = S2[0 * 264 + (4 + jj) * 33 + r] + S2[1 * 264 + (4 + jj) * 33 + r]
                     + S2[2 * 264 + (4 + jj) * 33 + r] + S2[3 * 264 + (4 + jj) * 33 + r]
                     + S1[(16 + jj) * 33 + r] + S1[660 + (16 + jj) * 33 + r]
                     + s_bh[jj];
            float z  = fast_sigmoid(zp);
            float hc = fast_tanh(hp);
            float hold = h4s[(j >> 2) * 128 + r * 4 + (j & 3)];
            float hn = z * hold + (1.f - z) * hc;
            g_h[(r0 + r) * HH + j] = hn;
            if (t == TT - 1)
                out[BB * TT * 2 + (r0 + r) * HH + j] = hn;
        }
        group_bar(fl, nj, base, ++ep);
    }

    // ---- final output row t=1023 from g_h ----
    if (nj == 0 && tid < 256) {
        int r = tid >> 3, kk = tid & 7;
        float o0 = 0.f, o1 = 0.f;
        for (int k = kk * 32; k < kk * 32 + 32; ++k) {
            float v = ldcg1(&g_h[(r0 + r) * HH + k]);
            o0 += v * s_Wo[k * 2];
            o1 += v * s_Wo[k * 2 + 1];
        }
        o0 += __shfl_xor_sync(0xffffffffu, o0, 1);
        o0 += __shfl_xor_sync(0xffffffffu, o0, 2);
        o0 += __shfl_xor_sync(0xffffffffu, o0, 4);
        o1 += __shfl_xor_sync(0xffffffffu, o1, 1);
        o1 += __shfl_xor_sync(0xffffffffu, o1, 2);
        o1 += __shfl_xor_sync(0xffffffffu, o1, 4);
        if (kk == 0) {
            float* op = out + (((r0 + r) * TT) + (TT - 1)) * 2;
            op[0] = o0 + s_bo[0];
            op[1] = o1 + s_bo[1];
        }
    }
}

extern "C" void kernel_launch(void* const* d_in, const int* in_sizes, int n_in,
                              void* d_out, int out_size) {
    const float* x   = (const float*)d_in[0];
    const float* h0  = (const float*)d_in[1];
    const float* Wa  = (const float*)d_in[2];
    const float* ba  = (const float*)d_in[3];
    const float* Wp1 = (const float*)d_in[4];
    const float* bp1 = (const float*)d_in[5];
    const float* Wp2 = (const float*)d_in[6];
    const float* bp2 = (const float*)d_in[7];
    const float* Wz  = (const float*)d_in[8];
    const float* bz  = (const float*)d_in[9];
    const float* Wh  = (const float*)d_in[10];
    const float* bh  = (const float*)d_in[11];
    const float* Wo  = (const float*)d_in[12];
    const float* bo  = (const float*)d_in[13];
    float* out = (float*)d_out;

    cudaFuncSetAttribute(pgjanet_kernel,
                         cudaFuncAttributeMaxDynamicSharedMemorySize, SMEM_BYTES);
    pgjanet_kernel<<<NCTA, NT, SMEM_BYTES>>>(
        x, h0, Wa, ba, Wp1, bp1, Wp2, bp2, Wz, bz, Wh, bh, Wo, bo, out);
}

// round 8
// speedup vs baseline: 1.0332x; 1.0332x over previous
#include <cuda_runtime.h>
#include <cuda_bf16.h>

#define NCTA 128
#define NT 640
#define TT 1024
#define BB 128
#define HH 256

__device__ float g_h[BB * HH];
__device__ float g_u[BB * HH];
__device__ unsigned g_flags[8][32][8];   // per 16-row tile, per CTA slice

__device__ __forceinline__ float4 ldcg4(const float4* p) {
    float4 v;
    asm volatile("ld.global.cg.v4.f32 {%0,%1,%2,%3}, [%4];"
                 : "=f"(v.x), "=f"(v.y), "=f"(v.z), "=f"(v.w) : "l"(p));
    return v;
}
__device__ __forceinline__ float ldcg1(const float* p) {
    float v;
    asm volatile("ld.global.cg.f32 %0, [%1];" : "=f"(v) : "l"(p));
    return v;
}
__device__ __forceinline__ float fast_tanh(float x) {
    float ax = fabsf(x);
    float e = __expf(2.0f * ax);
    float r = 1.0f - 2.0f / (e + 1.0f);
    return copysignf(r, x);
}
__device__ __forceinline__ float fast_sigmoid(float x) {
    return 1.0f / (1.0f + __expf(-x));
}

// Wait until all 32 CTAs of this tile-group reached epoch ep (then acquire).
__device__ __forceinline__ void bar_wait(unsigned* fl, unsigned base, unsigned ep) {
    if (threadIdx.x < 32) {
        unsigned v;
        unsigned* p = fl + threadIdx.x * 8;
        do {
            asm volatile("ld.relaxed.gpu.global.u32 %0, [%1];"
                         : "=r"(v) : "l"(p) : "memory");
        } while (__any_sync(0xffffffffu, (v - base) < ep));
        asm volatile("fence.acq_rel.gpu;" ::: "memory");
    }
    __syncthreads();
}
// Publish: all prior writes of this CTA, then store our epoch flag.
__device__ __forceinline__ void bar_signal(unsigned* fl, int nj, unsigned base, unsigned ep) {
    __syncthreads();
    if (threadIdx.x == 0) {
        asm volatile("fence.acq_rel.gpu;" ::: "memory");
        asm volatile("st.relaxed.gpu.global.u32 [%0], %1;"
                     :: "l"(fl + nj * 8), "r"(base + ep) : "memory");
    }
}

// SMEM layout (floats)
#define OFF_W1S 0                     // [256][40]
#define OFF_W2S 10240                 // [256][16]
#define OFF_HA  14336                 // [64][16][4]
#define OFF_HB  18432
#define OFF_UA  22528
#define OFF_UB  26624
#define OFF_S1A 30720                 // [4][40][17]
#define OFF_S1B 33440
#define OFF_S2  36160                 // [8][16][17]
#define OFF_AMPA 38336
#define OFF_COSA 38352
#define OFF_SINA 38368
#define OFF_AMPB 38384
#define OFF_COSB 38400
#define OFF_SINB 38416
#define OFF_W0  38432                 // [3][8]
#define OFF_B1  38456                 // [3][8]
#define OFF_BZ  38480                 // [8]
#define OFF_BH  38488                 // [8]
#define OFF_WOF 38496                 // [256][2]
#define OFF_BO  39008                 // [2]
#define SMEM_FLOATS 39012
#define SMEM_BYTES (SMEM_FLOATS * 4)

__global__ void __launch_bounds__(NT, 1) pgjanet_kernel(
    const float* __restrict__ x,   const float* __restrict__ h0,
    const float* __restrict__ Wa,  const float* __restrict__ ba,
    const float* __restrict__ Wp1, const float* __restrict__ bp1,
    const float* __restrict__ Wp2, const float* __restrict__ bp2,
    const float* __restrict__ Wz,  const float* __restrict__ bz,
    const float* __restrict__ Wh,  const float* __restrict__ bh,
    const float* __restrict__ Wo,  const float* __restrict__ bo,
    float* __restrict__ out)
{
    extern __shared__ float sm[];
    float* W1s = sm + OFF_W1S;
    float* W2s = sm + OFF_W2S;
    float* S2  = sm + OFF_S2;
    float* s_w0 = sm + OFF_W0;
    float* s_b1 = sm + OFF_B1;
    float* s_bz = sm + OFF_BZ;
    float* s_bh = sm + OFF_BH;
    float* s_Wo = sm + OFF_WOF;
    float* s_bo = sm + OFF_BO;

    const int tid  = threadIdx.x;
    const int lane = tid & 31;
    const int wid  = tid >> 5;
    const int nj = blockIdx.x & 31;   // column slice (8 h-cols, 40 G1-cols)
    const int g  = blockIdx.x >> 5;   // owns 16-row tiles 2g, 2g+1
    const int j0 = nj * 8;

    // per-tile contexts
    float* hT[2]  = { sm + OFF_HA,  sm + OFF_HB  };
    float* uT[2]  = { sm + OFF_UA,  sm + OFF_UB  };
    float* S1T[2] = { sm + OFF_S1A, sm + OFF_S1B };
    float* ampT[2] = { sm + OFF_AMPA, sm + OFF_AMPB };
    float* cosT[2] = { sm + OFF_COSA, sm + OFF_COSB };
    float* sinT[2] = { sm + OFF_SINA, sm + OFF_SINB };
    unsigned* flT[2] = { &g_flags[2 * g][0][0], &g_flags[2 * g + 1][0][0] };
    int r0T[2] = { (2 * g) * 16, (2 * g + 1) * 16 };

    unsigned baseT[2] = { 0, 0 };
    if (tid < 32) {
        asm volatile("ld.relaxed.gpu.global.u32 %0, [%1];"
                     : "=r"(baseT[0]) : "l"(flT[0] + nj * 8) : "memory");
        asm volatile("ld.relaxed.gpu.global.u32 %0, [%1];"
                     : "=r"(baseT[1]) : "l"(flT[1] + nj * 8) : "memory");
    }

    // ---- preload loop-invariant weights into SMEM ----
    for (int idx = tid; idx < 256 * 40; idx += NT) {
        int k = idx / 40, nn = idx % 40;
        int mat = nn >> 3, j = j0 + (nn & 7);
        float v;
        if      (mat == 0) v = Wa [(1 + k) * HH + j];
        else if (mat == 1) v = Wp1[(1 + k) * HH + j];
        else if (mat == 2) v = Wp2[(1 + k) * HH + j];
        else if (mat == 3) v = Wz [(HH + k) * HH + j];
        else               v = Wh [(HH + k) * HH + j];
        W1s[k * 40 + nn] = v;
    }
    for (int idx = tid; idx < 256 * 16; idx += NT) {
        int k = idx / 16, nn = idx % 16;
        int j = j0 + (nn & 7);
        W2s[k * 16 + nn] = (nn < 8) ? Wz[k * HH + j] : Wh[k * HH + j];
    }
    for (int idx = tid; idx < 512; idx += NT) s_Wo[idx] = Wo[idx];
    if (tid < 8) {
        int j = j0 + tid;
        s_w0[tid]      = Wa [j];  s_w0[8 + tid]  = Wp1[j];  s_w0[16 + tid] = Wp2[j];
        s_b1[tid]      = ba [j];  s_b1[8 + tid]  = bp1[j];  s_b1[16 + tid] = bp2[j];
        s_bz[tid] = bz[j];        s_bh[tid] = bh[j];
    }
    if (tid == 0) { s_bo[0] = bo[0]; s_bo[1] = bo[1]; }

    for (int t = 0; t < TT; ++t) {
        // ================= phase 1 for tile A, then tile B =================
        #pragma unroll
        for (int s = 0; s < 2; ++s) {
            float* h4 = hT[s];
            float* S1 = S1T[s];
            const int r0 = r0T[s];
            if (t > 0) bar_wait(flT[s], baseT[s], (unsigned)(2 * t));

            const float* hsrc = (t == 0) ? h0 : g_h;
            for (int idx = tid; idx < 16 * 64; idx += NT) {
                int r = idx >> 6, kc = idx & 63;
                float4 v = ldcg4((const float4*)(hsrc + (r0 + r) * HH) + kc);
                *(float4*)&h4[(kc * 16 + r) * 4] = v;
            }
            if (tid < 16) {
                const float* xp = x + (((r0 + tid) * TT) + t) * 2;
                float amp = __ldg(xp), ph = __ldg(xp + 1);
                ampT[s][tid] = amp;
                float sv, cv; sincosf(ph, &sv, &cv);
                sinT[s][tid] = sv; cosT[s][tid] = cv;
            }
            __syncthreads();

            // GEMM1: 20 warps = 5 col-groups(8) x 4 k-quarters; lane = row + 16*g2
            {
                int cg = wid % 5, kq = wid / 5;
                int r = lane & 15, g2 = lane >> 4;
                float a0 = 0.f, a1 = 0.f, a2 = 0.f, a3 = 0.f;
                const float* wp = W1s + cg * 8 + g2 * 4;
                #pragma unroll 4
                for (int kc = kq * 16; kc < kq * 16 + 16; ++kc) {
                    float4 hv = *(const float4*)&h4[(kc * 16 + r) * 4];
                    float4 w;
                    w = *(const float4*)&wp[(kc * 4 + 0) * 40];
                    a0 += hv.x * w.x; a1 += hv.x * w.y; a2 += hv.x * w.z; a3 += hv.x * w.w;
                    w = *(const float4*)&wp[(kc * 4 + 1) * 40];
                    a0 += hv.y * w.x; a1 += hv.y * w.y; a2 += hv.y * w.z; a3 += hv.y * w.w;
                    w = *(const float4*)&wp[(kc * 4 + 2) * 40];
                    a0 += hv.z * w.x; a1 += hv.z * w.y; a2 += hv.z * w.z; a3 += hv.z * w.w;
                    w = *(const float4*)&wp[(kc * 4 + 3) * 40];
                    a0 += hv.w * w.x; a1 += hv.w * w.y; a2 += hv.w * w.z; a3 += hv.w * w.w;
                }
                float* sp = S1 + kq * 680 + (cg * 8 + g2 * 4) * 17 + r;
                sp[0]  = a0;
                sp[17] = a1;
                sp[34] = a2;
                sp[51] = a3;
            }
            __syncthreads();

            // epilogue 1: a, p1, p2 -> u (128 threads)
            if (tid < 128) {
                int jj = tid & 7, r = tid >> 3;
                float sa = 0.f, sp1 = 0.f, sp2 = 0.f;
                #pragma unroll
                for (int q = 0; q < 4; ++q) {
                    sa  += S1[q * 680 + (0  + jj) * 17 + r];
                    sp1 += S1[q * 680 + (8  + jj) * 17 + r];
                    sp2 += S1[q * 680 + (16 + jj) * 17 + r];
                }
                float a  = fast_tanh(sa  + ampT[s][r] * s_w0[jj]      + s_b1[jj]);
                float p1 = fast_tanh(sp1 + cosT[s][r] * s_w0[8 + jj]  + s_b1[8 + jj]);
                float p2 = fast_tanh(sp2 + sinT[s][r] * s_w0[16 + jj] + s_b1[16 + jj]);
                g_u[(r0 + r) * HH + j0 + jj] =
                    a * p1 * p2 * (1.f - a) * (1.f - p1) * (1.f - p2);
            }
            bar_signal(flT[s], nj, baseT[s], (unsigned)(2 * t + 1));
        }

        // ================= phase 2 for tile A, then tile B =================
        #pragma unroll
        for (int s = 0; s < 2; ++s) {
            float* h4 = hT[s];
            float* u4 = uT[s];
            float* S1 = S1T[s];
            const int r0 = r0T[s];
            bar_wait(flT[s], baseT[s], (unsigned)(2 * t + 1));

            for (int idx = tid; idx < 16 * 64; idx += NT) {
                int r = idx >> 6, kc = idx & 63;
                float4 v = ldcg4((const float4*)(g_u + (r0 + r) * HH) + kc);
                *(float4*)&u4[(kc * 16 + r) * 4] = v;
            }
            __syncthreads();

            // GEMM2: warps 0-15 = 2 col-groups(8) x 8 k-eighths
            if (wid < 16) {
                int cg2 = wid & 1, ke = wid >> 1;
                int r = lane & 15, g2 = lane >> 4;
                float a0 = 0.f, a1 = 0.f, a2 = 0.f, a3 = 0.f;
                const float* wp = W2s + cg2 * 8 + g2 * 4;
                #pragma unroll 4
                for (int kc = ke * 8; kc < ke * 8 + 8; ++kc) {
                    float4 uv = *(const float4*)&u4[(kc * 16 + r) * 4];
                    float4 w;
                    w = *(const float4*)&wp[(kc * 4 + 0) * 16];
                    a0 += uv.x * w.x; a1 += uv.x * w.y; a2 += uv.x * w.z; a3 += uv.x * w.w;
                    w = *(const float4*)&wp[(kc * 4 + 1) * 16];
                    a0 += uv.y * w.x; a1 += uv.y * w.y; a2 += uv.y * w.z; a3 += uv.y * w.w;
                    w = *(const float4*)&wp[(kc * 4 + 2) * 16];
                    a0 += uv.z * w.x; a1 += uv.z * w.y; a2 += uv.z * w.z; a3 += uv.z * w.w;
                    w = *(const float4*)&wp[(kc * 4 + 3) * 16];
                    a0 += uv.w * w.x; a1 += uv.w * w.y; a2 += uv.w * w.z; a3 += uv.w * w.w;
                }
                float* sp = S2 + ke * 272 + (cg2 * 8 + g2 * 4) * 17 + r;
                sp[0]  = a0;
                sp[17] = a1;
                sp[34] = a2;
                sp[51] = a3;
            } else if (nj == 0 && t >= 1) {
                // warps 16-19: output projection for step t-1 from h4 (16 rows)
                int item = (wid - 16) * 32 + lane;   // 0..127
                int r = item >> 3, kk = item & 7;
                float o0 = 0.f, o1 = 0.f;
                for (int k = kk * 32; k < kk * 32 + 32; ++k) {
                    float v = h4[(k >> 2) * 64 + r * 4 + (k & 3)];
                    o0 += v * s_Wo[k * 2];
                    o1 += v * s_Wo[k * 2 + 1];
                }
                o0 += __shfl_xor_sync(0xffffffffu, o0, 1);
                o0 += __shfl_xor_sync(0xffffffffu, o0, 2);
                o0 += __shfl_xor_sync(0xffffffffu, o0, 4);
                o1 += __shfl_xor_sync(0xffffffffu, o1, 1);
                o1 += __shfl_xor_sync(0xffffffffu, o1, 2);
                o1 += __shfl_xor_sync(0xffffffffu, o1, 4);
                if (kk == 0) {
                    float* op = out + (((r0 + r) * TT) + (t - 1)) * 2;
                    op[0] = o0 + s_bo[0];
                    op[1] = o1 + s_bo[1];
                }
            }
            __syncthreads();

            // epilogue 2: z, h_cand, h_new (128 threads)
            if (tid < 128) {
                int jj = tid & 7, r = tid >> 3;
                int j = j0 + jj;
                float zp = s_bz[jj], hp = s_bh[jj];
                #pragma unroll
                for (int e = 0; e < 8; ++e) {
                    zp += S2[e * 272 + jj * 17 + r];
                    hp += S2[e * 272 + (8 + jj) * 17 + r];
                }
                #pragma unroll
                for (int q = 0; q < 4; ++q) {
                    zp += S1[q * 680 + (24 + jj) * 17 + r];
                    hp += S1[q * 680 + (32 + jj) * 17 + r];
                }
                float z  = fast_sigmoid(zp);
                float hc = fast_tanh(hp);
                float hold = h4[(j >> 2) * 64 + r * 4 + (j & 3)];
                float hn = z * hold + (1.f - z) * hc;
                g_h[(r0 + r) * HH + j] = hn;
                if (t == TT - 1)
                    out[BB * TT * 2 + (r0 + r) * HH + j] = hn;
            }
            bar_signal(flT[s], nj, baseT[s], (unsigned)(2 * t + 2));
        }
    }

    // ---- final output row t=1023 from g_h (after final barriers) ----
    bar_wait(flT[0], baseT[0], (unsigned)(2 * TT));
    bar_wait(flT[1], baseT[1], (unsigned)(2 * TT));
    if (nj == 0 && tid < 256) {
        int s = tid >> 7;
        int item = tid & 127;
        int r = item >> 3, kk = item & 7;
        int row = r0T[s] + r;
        float o0 = 0.f, o1 = 0.f;
        for (int k = kk * 32; k < kk * 32 + 32; ++k) {
            float v = ldcg1(&g_h[row * HH + k]);
            o0 += v * s_Wo[k * 2];
            o1 += v * s_Wo[k * 2 + 1];
        }
        o0 += __shfl_xor_sync(0xffffffffu, o0, 1);
        o0 += __shfl_xor_sync(0xffffffffu, o0, 2);
        o0 += __shfl_xor_sync(0xffffffffu, o0, 4);
        o1 += __shfl_xor_sync(0xffffffffu, o1, 1);
        o1 += __shfl_xor_sync(0xffffffffu, o1, 2);
        o1 += __shfl_xor_sync(0xffffffffu, o1, 4);
        if (kk == 0) {
            float* op = out + ((row * TT) + (TT - 1)) * 2;
            op[0] = o0 + s_bo[0];
            op[1] = o1 + s_bo[1];
        }
    }
}

extern "C" void kernel_launch(void* const* d_in, const int* in_sizes, int n_in,
                              void* d_out, int out_size) {
    const float* x   = (const float*)d_in[0];
    const float* h0  = (const float*)d_in[1];
    const float* Wa  = (const float*)d_in[2];
    const float* ba  = (const float*)d_in[3];
    const float* Wp1 = (const float*)d_in[4];
    const float* bp1 = (const float*)d_in[5];
    const float* Wp2 = (const float*)d_in[6];
    const float* bp2 = (const float*)d_in[7];
    const float* Wz  = (const float*)d_in[8];
    const float* bz  = (const float*)d_in[9];
    const float* Wh  = (const float*)d_in[10];
    const float* bh  = (const float*)d_in[11];
    const float* Wo  = (const float*)d_in[12];
    const float* bo  = (const float*)d_in[13];
    float* out = (float*)d_out;

    cudaFuncSetAttribute(pgjanet_kernel,
                         cudaFuncAttributeMaxDynamicSharedMemorySize, SMEM_BYTES);
    pgjanet_kernel<<<NCTA, NT, SMEM_BYTES>>>(
        x, h0, Wa, ba, Wp1, bp1, Wp2, bp2, Wz, bz, Wh, bh, Wo, bo, out);
}

// round 9
// speedup vs baseline: 1.1820x; 1.1440x over previous
#include <cuda_runtime.h>
#include <cuda_bf16.h>

#define NCTA 128
#define NT 640
#define TT 1024
#define BB 128
#define HH 256

__device__ float g_h[BB * HH];
__device__ float g_u[BB * HH];
__device__ unsigned g_flags[4][32][8];

__device__ __forceinline__ float4 ldcg4(const float4* p) {
    float4 v;
    asm volatile("ld.global.cg.v4.f32 {%0,%1,%2,%3}, [%4];"
                 : "=f"(v.x), "=f"(v.y), "=f"(v.z), "=f"(v.w) : "l"(p));
    return v;
}
__device__ __forceinline__ float ldcg1(const float* p) {
    float v;
    asm volatile("ld.global.cg.f32 %0, [%1];" : "=f"(v) : "l"(p));
    return v;
}
__device__ __forceinline__ float fast_tanh(float x) {
    float ax = fabsf(x);
    float e = __expf(2.0f * ax);
    float r = 1.0f - 2.0f / (e + 1.0f);
    return copysignf(r, x);
}
__device__ __forceinline__ float fast_sigmoid(float x) {
    return 1.0f / (1.0f + __expf(-x));
}

// Row-group barrier: 32 CTAs (same mi), flag store + 32-lane poll in warp 0.
__device__ __forceinline__ void group_bar(unsigned* fl, int nj, unsigned base, unsigned ep) {
    __syncthreads();
    if (threadIdx.x < 32) {
        if (threadIdx.x == 0) {
            asm volatile("fence.acq_rel.gpu;" ::: "memory");
            asm volatile("st.relaxed.gpu.global.u32 [%0], %1;"
                         :: "l"(fl + nj * 8), "r"(base + ep) : "memory");
        }
        unsigned v;
        unsigned* p = fl + threadIdx.x * 8;
        do {
            asm volatile("ld.relaxed.gpu.global.u32 %0, [%1];"
                         : "=r"(v) : "l"(p) : "memory");
        } while (__any_sync(0xffffffffu, (v - base) < ep));
        asm volatile("fence.acq_rel.gpu;" ::: "memory");
    }
    __syncthreads();
}

// SMEM layout (floats)
#define OFF_W1S 0                         // [256][40]
#define OFF_W2S 10240                     // [256][16]
#define OFF_H4S 14336                     // [64][32][4]
#define OFF_U4S 22528                     // [64][32][4]
#define OFF_S1  30720                     // [4][40][33]  k-quarter partials
#define OFF_S2  36000                     // [8][16][33]  k-eighth partials
#define OFF_AMP 40224                     // [32]
#define OFF_COS 40256
#define OFF_SIN 40288
#define OFF_W0  40320                     // [3][8]
#define OFF_B1  40344                     // [3][8]
#define OFF_BZ  40368                     // [8]
#define OFF_BH  40376                     // [8]
#define OFF_WOF 40384                     // [256][2]
#define OFF_BO  40896                     // [2]
#define SMEM_FLOATS 40898
#define SMEM_BYTES (SMEM_FLOATS * 4)

__global__ void __launch_bounds__(NT, 1) pgjanet_kernel(
    const float* __restrict__ x,   const float* __restrict__ h0,
    const float* __restrict__ Wa,  const float* __restrict__ ba,
    const float* __restrict__ Wp1, const float* __restrict__ bp1,
    const float* __restrict__ Wp2, const float* __restrict__ bp2,
    const float* __restrict__ Wz,  const float* __restrict__ bz,
    const float* __restrict__ Wh,  const float* __restrict__ bh,
    const float* __restrict__ Wo,  const float* __restrict__ bo,
    float* __restrict__ out)
{
    extern __shared__ float sm[];
    float* W1s = sm + OFF_W1S;
    float* W2s = sm + OFF_W2S;
    float* h4s = sm + OFF_H4S;
    float* u4s = sm + OFF_U4S;
    float* S1  = sm + OFF_S1;
    float* S2  = sm + OFF_S2;
    float* s_amp = sm + OFF_AMP;
    float* s_cos = sm + OFF_COS;
    float* s_sin = sm + OFF_SIN;
    float* s_w0  = sm + OFF_W0;
    float* s_b1  = sm + OFF_B1;
    float* s_bz  = sm + OFF_BZ;
    float* s_bh  = sm + OFF_BH;
    float* s_Wo  = sm + OFF_WOF;
    float* s_bo  = sm + OFF_BO;

    const int tid  = threadIdx.x;
    const int lane = tid & 31;
    const int wid  = tid >> 5;
    const int nj = blockIdx.x & 31;   // column slice (8 cols)
    const int mi = blockIdx.x >> 5;   // row group (32 rows)
    const int j0 = nj * 8;
    const int r0 = mi * 32;

    unsigned* fl = &g_flags[mi][0][0];

    unsigned base = 0;
    if (tid < 32)
        asm volatile("ld.relaxed.gpu.global.u32 %0, [%1];"
                     : "=r"(base) : "l"(fl + nj * 8) : "memory");

    // ---- preload loop-invariant weights into SMEM ----
    for (int idx = tid; idx < 256 * 40; idx += NT) {
        int k = idx / 40, nn = idx % 40;
        int mat = nn >> 3, j = j0 + (nn & 7);
        float v;
        if      (mat == 0) v = Wa [(1 + k) * HH + j];
        else if (mat == 1) v = Wp1[(1 + k) * HH + j];
        else if (mat == 2) v = Wp2[(1 + k) * HH + j];
        else if (mat == 3) v = Wz [(HH + k) * HH + j];
        else               v = Wh [(HH + k) * HH + j];
        W1s[k * 40 + nn] = v;
    }
    for (int idx = tid; idx < 256 * 16; idx += NT) {
        int k = idx / 16, nn = idx % 16;
        int j = j0 + (nn & 7);
        W2s[k * 16 + nn] = (nn < 8) ? Wz[k * HH + j] : Wh[k * HH + j];
    }
    for (int idx = tid; idx < 512; idx += NT) s_Wo[idx] = Wo[idx];
    if (tid < 8) {
        int j = j0 + tid;
        s_w0[tid]      = Wa [j];  s_w0[8 + tid]  = Wp1[j];  s_w0[16 + tid] = Wp2[j];
        s_b1[tid]      = ba [j];  s_b1[8 + tid]  = bp1[j];  s_b1[16 + tid] = bp2[j];
        s_bz[tid] = bz[j];        s_bh[tid] = bh[j];
    }
    if (tid == 0) { s_bo[0] = bo[0]; s_bo[1] = bo[1]; }

    unsigned ep = 0;

    for (int t = 0; t < TT; ++t) {
        // ---- stage 1: load h tile into SMEM ([kc][row][4]) ----
        const float* hsrc = (t == 0) ? h0 : g_h;
        for (int idx = tid; idx < 32 * 64; idx += NT) {
            int r = idx >> 6, kc = idx & 63;
            float4 v = ldcg4((const float4*)(hsrc + (r0 + r) * HH) + kc);
            *(float4*)&h4s[(kc * 32 + r) * 4] = v;
        }
        if (tid < 32) {
            const float* xp = x + (((r0 + tid) * TT) + t) * 2;
            float amp = __ldg(xp), ph = __ldg(xp + 1);
            s_amp[tid] = amp;
            float sv, cv; sincosf(ph, &sv, &cv);
            s_sin[tid] = sv; s_cos[tid] = cv;
        }
        __syncthreads();

        // ---- GEMM1: 20 warps = 5 col-groups (8 cols) x 4 k-quarters ----
        {
            int cg = wid % 5, kq = wid / 5;
            float a0 = 0.f, a1 = 0.f, a2 = 0.f, a3 = 0.f;
            float a4 = 0.f, a5 = 0.f, a6 = 0.f, a7 = 0.f;
            const float* wp = W1s + cg * 8;
            #pragma unroll 4
            for (int m = kq * 16; m < kq * 16 + 16; ++m) {
                float4 hv = *(const float4*)&h4s[(m * 32 + lane) * 4];
                #pragma unroll
                for (int d = 0; d < 4; ++d) {
                    float hk = (d == 0) ? hv.x : (d == 1) ? hv.y : (d == 2) ? hv.z : hv.w;
                    float4 w0 = *(const float4*)&wp[(4 * m + d) * 40];
                    float4 w1 = *(const float4*)&wp[(4 * m + d) * 40 + 4];
                    a0 += hk * w0.x; a1 += hk * w0.y; a2 += hk * w0.z; a3 += hk * w0.w;
                    a4 += hk * w1.x; a5 += hk * w1.y; a6 += hk * w1.z; a7 += hk * w1.w;
                }
            }
            float* s = S1 + kq * 1320 + (cg * 8) * 33 + lane;
            s[0]      = a0; s[33]     = a1; s[66]     = a2; s[99]     = a3;
            s[132]    = a4; s[165]    = a5; s[198]    = a6; s[231]    = a7;
        }
        __syncthreads();

        // ---- epilogue 1: a, p1, p2 -> u ----
        if (tid < 256) {
            int jj = tid & 7, r = tid >> 3;
            float sa = 0.f, sp1 = 0.f, sp2 = 0.f;
            #pragma unroll
            for (int q = 0; q < 4; ++q) {
                sa  += S1[q * 1320 + (0  + jj) * 33 + r];
                sp1 += S1[q * 1320 + (8  + jj) * 33 + r];
                sp2 += S1[q * 1320 + (16 + jj) * 33 + r];
            }
            float a  = fast_tanh(sa  + s_amp[r] * s_w0[jj]      + s_b1[jj]);
            float p1 = fast_tanh(sp1 + s_cos[r] * s_w0[8 + jj]  + s_b1[8 + jj]);
            float p2 = fast_tanh(sp2 + s_sin[r] * s_w0[16 + jj] + s_b1[16 + jj]);
            g_u[(r0 + r) * HH + j0 + jj] =
                a * p1 * p2 * (1.f - a) * (1.f - p1) * (1.f - p2);
        }
        group_bar(fl, nj, base, ++ep);

        // ---- stage 2: load u tile ----
        for (int idx = tid; idx < 32 * 64; idx += NT) {
            int r = idx >> 6, kc = idx & 63;
            float4 v = ldcg4((const float4*)(g_u + (r0 + r) * HH) + kc);
            *(float4*)&u4s[(kc * 32 + r) * 4] = v;
        }
        __syncthreads();

        // ---- GEMM2: warps 0-15 = 2 col-groups (8 cols) x 8 k-eighths ----
        if (wid < 16) {
            int cg2 = wid & 1, ke = wid >> 1;
            float a0 = 0.f, a1 = 0.f, a2 = 0.f, a3 = 0.f;
            float a4 = 0.f, a5 = 0.f, a6 = 0.f, a7 = 0.f;
            const float* wp = W2s + cg2 * 8;
            #pragma unroll 4
            for (int m = ke * 8; m < ke * 8 + 8; ++m) {
                float4 uv = *(const float4*)&u4s[(m * 32 + lane) * 4];
                #pragma unroll
                for (int d = 0; d < 4; ++d) {
                    float uk = (d == 0) ? uv.x : (d == 1) ? uv.y : (d == 2) ? uv.z : uv.w;
                    float4 w0 = *(const float4*)&wp[(4 * m + d) * 16];
                    float4 w1 = *(const float4*)&wp[(4 * m + d) * 16 + 4];
                    a0 += uk * w0.x; a1 += uk * w0.y; a2 += uk * w0.z; a3 += uk * w0.w;
                    a4 += uk * w1.x; a5 += uk * w1.y; a6 += uk * w1.z; a7 += uk * w1.w;
                }
            }
            float* s = S2 + ke * 528 + (cg2 * 8) * 33 + lane;
            s[0]   = a0; s[33]  = a1; s[66]  = a2; s[99]  = a3;
            s[132] = a4; s[165] = a5; s[198] = a6; s[231] = a7;
        } else if (nj == 0 && t >= 1) {
            // warps 16-19: output projection for step t-1 from h4s
            #pragma unroll
            for (int it = 0; it < 2; ++it) {
                int item = it * 128 + (wid - 16) * 32 + lane;
                int r = item >> 3, kk = item & 7;
                float o0 = 0.f, o1 = 0.f;
                for (int k = kk * 32; k < kk * 32 + 32; ++k) {
                    float v = h4s[(k >> 2) * 128 + r * 4 + (k & 3)];
                    o0 += v * s_Wo[k * 2];
                    o1 += v * s_Wo[k * 2 + 1];
                }
                o0 += __shfl_xor_sync(0xffffffffu, o0, 1);
                o0 += __shfl_xor_sync(0xffffffffu, o0, 2);
                o0 += __shfl_xor_sync(0xffffffffu, o0, 4);
                o1 += __shfl_xor_sync(0xffffffffu, o1, 1);
                o1 += __shfl_xor_sync(0xffffffffu, o1, 2);
                o1 += __shfl_xor_sync(0xffffffffu, o1, 4);
                if (kk == 0) {
                    float* op = out + (((r0 + r) * TT) + (t - 1)) * 2;
                    op[0] = o0 + s_bo[0];
                    op[1] = o1 + s_bo[1];
                }
            }
        }
        __syncthreads();

        // ---- epilogue 2: z, h_cand, h_new ----
        if (tid < 256) {
            int jj = tid & 7, r = tid >> 3;
            int j = j0 + jj;
            float zp = s_bz[jj], hp = s_bh[jj];
            #pragma unroll
            for (int e = 0; e < 8; ++e) {
                zp += S2[e * 528 + jj * 33 + r];
                hp += S2[e * 528 + (8 + jj) * 33 + r];
            }
            #pragma unroll
            for (int q = 0; q < 4; ++q) {
                zp += S1[q * 1320 + (24 + jj) * 33 + r];
                hp += S1[q * 1320 + (32 + jj) * 33 + r];
            }
            float z  = fast_sigmoid(zp);
            float hc = fast_tanh(hp);
            float hold = h4s[(j >> 2) * 128 + r * 4 + (j & 3)];
            float hn = z * hold + (1.f - z) * hc;
            g_h[(r0 + r) * HH + j] = hn;
            if (t == TT - 1)
                out[BB * TT * 2 + (r0 + r) * HH + j] = hn;
        }
        group_bar(fl, nj, base, ++ep);
    }

    // ---- final output row t=1023 from g_h ----
    if (nj == 0 && tid < 256) {
        int r = tid >> 3, kk = tid & 7;
        float o0 = 0.f, o1 = 0.f;
        for (int k = kk * 32; k < kk * 32 + 32; ++k) {
            float v = ldcg1(&g_h[(r0 + r) * HH + k]);
            o0 += v * s_Wo[k * 2];
            o1 += v * s_Wo[k * 2 + 1];
        }
        o0 += __shfl_xor_sync(0xffffffffu, o0, 1);
        o0 += __shfl_xor_sync(0xffffffffu, o0, 2);
        o0 += __shfl_xor_sync(0xffffffffu, o0, 4);
        o1 += __shfl_xor_sync(0xffffffffu, o1, 1);
        o1 += __shfl_xor_sync(0xffffffffu, o1, 2);
        o1 += __shfl_xor_sync(0xffffffffu, o1, 4);
        if (kk == 0) {
            float* op = out + (((r0 + r) * TT) + (TT - 1)) * 2;
            op[0] = o0 + s_bo[0];
            op[1] = o1 + s_bo[1];
        }
    }
}

extern "C" void kernel_launch(void* const* d_in, const int* in_sizes, int n_in,
                              void* d_out, int out_size) {
    const float* x   = (const float*)d_in[0];
    const float* h0  = (const float*)d_in[1];
    const float* Wa  = (const float*)d_in[2];
    const float* ba  = (const float*)d_in[3];
    const float* Wp1 = (const float*)d_in[4];
    const float* bp1 = (const float*)d_in[5];
    const float* Wp2 = (const float*)d_in[6];
    const float* bp2 = (const float*)d_in[7];
    const float* Wz  = (const float*)d_in[8];
    const float* bz  = (const float*)d_in[9];
    const float* Wh  = (const float*)d_in[10];
    const float* bh  = (const float*)d_in[11];
    const float* Wo  = (const float*)d_in[12];
    const float* bo  = (const float*)d_in[13];
    float* out = (float*)d_out;

    cudaFuncSetAttribute(pgjanet_kernel,
                         cudaFuncAttributeMaxDynamicSharedMemorySize, SMEM_BYTES);
    pgjanet_kernel<<<NCTA, NT, SMEM_BYTES>>>(
        x, h0, Wa, ba, Wp1, bp1, Wp2, bp2, Wz, bz, Wh, bh, Wo, bo, out);
}